// round 1
// baseline (speedup 1.0000x reference)
#include <cuda_runtime.h>
#include <cuda_bf16.h>

// Problem constants (fixed by the reference):
// L, R: [N, C, H, W] fp32 ; out: [N, C, D, H, W] fp32
// out[n,c,d,h,w] = (w >= d) ? L[n,c,h,w] - R[n,c,h,w-d] : 1.0f
static constexpr int Nn = 2;
static constexpr int Cc = 32;
static constexpr int Hh = 128;
static constexpr int Ww = 256;
static constexpr int Dd = 48;

static constexpr int W4   = Ww / 4;        // 64 float4 per row
static constexpr int NCH  = Nn * Cc * Hh;  // 8192 (n*c, h) rows
static constexpr int HW   = Hh * Ww;       // elements per (d) plane within one nc
static constexpr int HW4  = HW / 4;        // float4 stride between d planes

__global__ __launch_bounds__(256)
void cost_volume_kernel(const float* __restrict__ L,
                        const float* __restrict__ R,
                        float* __restrict__ out)
{
    // One thread per (nc*H row, w4) column; loops over all D disparities.
    int tid = blockIdx.x * 256 + threadIdx.x;        // 0 .. NCH*W4-1 (exact grid)
    int w4  = tid & (W4 - 1);                        // 0..63
    int row = tid >> 6;                              // nc*H + h, 0..8191
    int h   = row & (Hh - 1);
    int nc  = row >> 7;                              // 0..63

    int w = w4 * 4;

    const float* __restrict__ lrow = L + (size_t)row * Ww;
    const float* __restrict__ rrow = R + (size_t)row * Ww;

    // L operand: loaded once, reused for all 48 disparities.
    float4 lv = *reinterpret_cast<const float4*>(lrow + w);

    // Output base for d=0 plane of this (nc, h, w) column.
    float4* outp = reinterpret_cast<float4*>(
        out + ((size_t)(nc * Dd) * Hh + h) * (size_t)Ww + w);

    #pragma unroll 8
    for (int d = 0; d < Dd; ++d) {
        // Clamped source indices (matches reference's clip; keeps loads in-bounds).
        int s0 = w + 0 - d; s0 = s0 < 0 ? 0 : s0;
        int s1 = w + 1 - d; s1 = s1 < 0 ? 0 : s1;
        int s2 = w + 2 - d; s2 = s2 < 0 ? 0 : s2;
        int s3 = w + 3 - d; s3 = s3 < 0 ? 0 : s3;

        float r0 = __ldg(rrow + s0);
        float r1 = __ldg(rrow + s1);
        float r2 = __ldg(rrow + s2);
        float r3 = __ldg(rrow + s3);

        float4 o;
        o.x = (w + 0 >= d) ? (lv.x - r0) : 1.0f;
        o.y = (w + 1 >= d) ? (lv.y - r1) : 1.0f;
        o.z = (w + 2 >= d) ? (lv.z - r2) : 1.0f;
        o.w = (w + 3 >= d) ? (lv.w - r3) : 1.0f;

        outp[(size_t)d * HW4] = o;   // STG.128, coalesced across the warp
    }
}

extern "C" void kernel_launch(void* const* d_in, const int* in_sizes, int n_in,
                              void* d_out, int out_size)
{
    const float* L = (const float*)d_in[0];
    const float* R = (const float*)d_in[1];
    float* out = (float*)d_out;

    const int total_threads = NCH * W4;   // 524,288
    const int block = 256;
    const int grid = total_threads / block;  // 2048, exact

    cost_volume_kernel<<<grid, block>>>(L, R, out);
}

// round 2
// speedup vs baseline: 1.0260x; 1.0260x over previous
#include <cuda_runtime.h>
#include <cuda_bf16.h>

// L, R: [N, C, H, W] fp32 ; out: [N, C, D, H, W] fp32
// out[n,c,d,h,w] = (w >= d) ? L[n,c,h,w] - R[n,c,h,w-d] : 1.0f
static constexpr int Nn = 2;
static constexpr int Cc = 32;
static constexpr int Hh = 128;
static constexpr int Ww = 256;
static constexpr int Dd = 48;

static constexpr int W4   = Ww / 4;        // 64 float4 per row
static constexpr int NCH  = Nn * Cc * Hh;  // 8192 rows
static constexpr int HW   = Hh * Ww;
static constexpr int HW4  = HW / 4;        // float4 stride between d planes

static constexpr int DCHUNK = 16;          // disparities per register window

__global__ __launch_bounds__(256)
void cost_volume_kernel(const float* __restrict__ L,
                        const float* __restrict__ R,
                        float* __restrict__ out)
{
    int tid = blockIdx.x * 256 + threadIdx.x;   // exact grid: NCH*W4 threads
    int w4  = tid & (W4 - 1);                   // 0..63
    int row = tid >> 6;                         // 0..8191
    int h   = row & (Hh - 1);
    int nc  = row >> 7;

    int w = w4 * 4;

    const float4* __restrict__ rrow4 =
        reinterpret_cast<const float4*>(R + (size_t)row * Ww);

    // L operand: one LDG.128, reused for all 48 disparities.
    float4 lv = __ldg(reinterpret_cast<const float4*>(L + (size_t)row * Ww) + w4);

    float4* outp = reinterpret_cast<float4*>(
        out + ((size_t)(nc * Dd) * Hh + h) * (size_t)Ww + w);

    #pragma unroll
    for (int c = 0; c < Dd; c += DCHUNK) {
        // Register window over r[w-c-16 .. w-c+7] : 6 aligned float4 loads.
        // Addresses clamped to row start; clamped garbage is masked by (w>=d).
        float win[24];
        #pragma unroll
        for (int j = 0; j < 6; ++j) {
            int idx = w4 - (c >> 2) - 4 + j;
            idx = idx < 0 ? 0 : idx;
            float4 v = __ldg(rrow4 + idx);
            win[4 * j + 0] = v.x;
            win[4 * j + 1] = v.y;
            win[4 * j + 2] = v.z;
            win[4 * j + 3] = v.w;
        }

        // 16 disparities from the window; all win[] indices are compile-time
        // constants after unrolling, so the window stays in registers.
        #pragma unroll
        for (int dd = 0; dd < DCHUNK; ++dd) {
            const int d = c + dd;
            // element r[w+k-d] lives at win[16 + k - dd]
            float4 o;
            o.x = (w + 0 >= d) ? (lv.x - win[16 - dd]) : 1.0f;
            o.y = (w + 1 >= d) ? (lv.y - win[17 - dd]) : 1.0f;
            o.z = (w + 2 >= d) ? (lv.z - win[18 - dd]) : 1.0f;
            o.w = (w + 3 >= d) ? (lv.w - win[19 - dd]) : 1.0f;
            outp[(size_t)d * HW4] = o;   // coalesced STG.128
        }
    }
}

extern "C" void kernel_launch(void* const* d_in, const int* in_sizes, int n_in,
                              void* d_out, int out_size)
{
    const float* L = (const float*)d_in[0];
    const float* R = (const float*)d_in[1];
    float* out = (float*)d_out;

    const int total_threads = NCH * W4;       // 524,288
    const int block = 256;
    const int grid  = total_threads / block;  // 2048
    cost_volume_kernel<<<grid, block>>>(L, R, out);
}

// round 3
// speedup vs baseline: 1.1311x; 1.1025x over previous
#include <cuda_runtime.h>
#include <cuda_bf16.h>

// L, R: [N, C, H, W] fp32 ; out: [N, C, D, H, W] fp32
// out[n,c,d,h,w] = (w >= d) ? L[n,c,h,w] - R[n,c,h,w-d] : 1.0f
static constexpr int Nn = 2;
static constexpr int Cc = 32;
static constexpr int Hh = 128;
static constexpr int Ww = 256;
static constexpr int Dd = 48;

static constexpr int W4   = Ww / 4;        // 64 float4 per row
static constexpr int NCH  = Nn * Cc * Hh;  // 8192 rows
static constexpr int HW   = Hh * Ww;
static constexpr int HW4  = HW / 4;        // float4 stride between d planes

static constexpr int DCHUNK = 24;          // disparities per register window
static constexpr int WINF4  = DCHUNK / 4 + 2;  // 8 float4 = 32 floats

__global__ __launch_bounds__(256)
void cost_volume_kernel(const float* __restrict__ L,
                        const float* __restrict__ R,
                        float* __restrict__ out)
{
    int tid = blockIdx.x * 256 + threadIdx.x;   // exact grid: NCH*W4 threads
    int w4  = tid & (W4 - 1);                   // 0..63
    int row = tid >> 6;                         // 0..8191
    int h   = row & (Hh - 1);
    int nc  = row >> 7;

    int w = w4 * 4;

    const float4* __restrict__ rrow4 =
        reinterpret_cast<const float4*>(R + (size_t)row * Ww);

    // L operand: one LDG.128, reused for all 48 disparities.
    float4 lv = __ldg(reinterpret_cast<const float4*>(L + (size_t)row * Ww) + w4);

    float4* outp = reinterpret_cast<float4*>(
        out + ((size_t)(nc * Dd) * Hh + h) * (size_t)Ww + w);

    #pragma unroll
    for (int c = 0; c < Dd; c += DCHUNK) {
        // Register window over r[w-c-(DCHUNK-4) .. w-c+7] : WINF4 aligned
        // float4 loads. Addresses clamped to row start; clamped garbage is
        // masked to 1.0 by the (w>=d) predicate.
        float win[4 * WINF4];
        #pragma unroll
        for (int j = 0; j < WINF4; ++j) {
            int idx = w4 - (c >> 2) - (WINF4 - 2) + j;
            idx = idx < 0 ? 0 : idx;
            float4 v = __ldg(rrow4 + idx);
            win[4 * j + 0] = v.x;
            win[4 * j + 1] = v.y;
            win[4 * j + 2] = v.z;
            win[4 * j + 3] = v.w;
        }

        // Base of the "aligned with w" position inside the window:
        // element r[w+k-d] (d = c+dd) lives at win[BASE + k - dd]
        constexpr int BASE = 4 * (WINF4 - 2);

        #pragma unroll
        for (int dd = 0; dd < DCHUNK; ++dd) {
            const int d = c + dd;
            float4 o;
            o.x = (w + 0 >= d) ? (lv.x - win[BASE + 0 - dd]) : 1.0f;
            o.y = (w + 1 >= d) ? (lv.y - win[BASE + 1 - dd]) : 1.0f;
            o.z = (w + 2 >= d) ? (lv.z - win[BASE + 2 - dd]) : 1.0f;
            o.w = (w + 3 >= d) ? (lv.w - win[BASE + 3 - dd]) : 1.0f;
            // Streaming store: evict-first in L2 (zero-reuse output stream).
            __stcs(outp + (size_t)d * HW4, o);
        }
    }
}

extern "C" void kernel_launch(void* const* d_in, const int* in_sizes, int n_in,
                              void* d_out, int out_size)
{
    const float* L = (const float*)d_in[0];
    const float* R = (const float*)d_in[1];
    float* out = (float*)d_out;

    const int total_threads = NCH * W4;       // 524,288
    const int block = 256;
    const int grid  = total_threads / block;  // 2048
    cost_volume_kernel<<<grid, block>>>(L, R, out);
}